// round 15
// baseline (speedup 1.0000x reference)
#include <cuda_runtime.h>
#include <cuda_bf16.h>

// Fixed problem shapes
#define B    8
#define T    16
#define C    64
#define H    56
#define W_   56
#define HW   (H * W_)          // 3136
#define HW4  (HW / 4)          // 784 (float4)
#define HW2  (HW / 2)          // 1568 (float2)
#define DIM  8
#define POOL 7
#define FEAT (DIM * DIM)       // 64
#define DH   64
#define BC   (B * C)           // 512
#define LN_EPS 1e-5f

#define CHUNK_B 2              // pipeline chunk = 2 batches (25.7 MB)
#define NB_POOL 2048           // CHUNK_B*T*C pool blocks per chunk
#define NB_ATTN 128            // CHUNK_B*C
#define NB_OUT  896            // 7 * CHUNK_B*C

typedef unsigned long long ull;

// Static device scratch (no allocations allowed)
__device__ float g_pool[BC * T * FEAT];   // 2 MB
__device__ ull   g_attn2[BC * T * T];     // packed {w,w}, 1 MB

__device__ __forceinline__ ull ffma2(ull a, ull b, ull c)
{
    ull d;
    asm("fma.rn.f32x2 %0, %1, %2, %3;" : "=l"(d) : "l"(a), "l"(b), "l"(c));
    return d;
}

// ---------------------------------------------------------------------------
// Role: pool one (b,t,c) slice. 256 threads. smem: 12544 B stage.
// ---------------------------------------------------------------------------
__device__ __forceinline__ void pool_role(float* stage, const float* __restrict__ x,
                                          int slice)
{
    const int c = slice % C;
    const int t = (slice / C) % T;
    const int b = slice / (T * C);
    const int tid = threadIdx.x;

    const float4* xs = reinterpret_cast<const float4*>(x) + (long)slice * HW4;
    float4* st4 = reinterpret_cast<float4*>(stage);
    st4[tid]        = xs[tid];
    st4[tid + 256]  = xs[tid + 256];
    st4[tid + 512]  = xs[tid + 512];
    if (tid < 16) st4[tid + 768] = xs[tid + 768];
    __syncthreads();

    const int cell = tid >> 2;
    const int sub  = tid & 3;
    const int ci   = cell >> 3;
    const int cj   = cell & 7;

    const float* r0 = stage + (ci * POOL + sub) * W_ + cj * POOL;
    float sum = 0.f;
    #pragma unroll
    for (int jj = 0; jj < POOL; jj++) sum += r0[jj];
    if (sub < 3) {
        #pragma unroll
        for (int jj = 0; jj < POOL; jj++) sum += r0[4 * W_ + jj];
    }
    sum += __shfl_xor_sync(0xffffffffu, sum, 1);
    sum += __shfl_xor_sync(0xffffffffu, sum, 2);
    if (sub == 0)
        g_pool[((b * C + c) * T + t) * FEAT + cell] = sum * (1.f / (POOL * POOL));
}

// ---------------------------------------------------------------------------
// Role: attention for one (b,c). 256 threads. smem: s(4K)+qk(8K)+mu/rs.
// ---------------------------------------------------------------------------
__device__ __forceinline__ void attn_role(float* smf,
                                          const float* __restrict__ pos,
                                          const float* __restrict__ Wqk,
                                          const float* __restrict__ gamma,
                                          const float* __restrict__ beta,
                                          int bc)
{
    float* s  = smf;                 // [T][FEAT] 1024 floats
    float* qk = smf + 1024;          // [T][2*DH] 2048 floats
    float* mu = smf + 3072;          // [T]
    float* rs = smf + 3088;          // [T]
    const int tid = threadIdx.x;

    {
        const float* gp = g_pool + bc * (T * FEAT);
        const float* pp = pos    + bc * (T * FEAT);
        #pragma unroll
        for (int i = tid; i < T * FEAT; i += 256) s[i] = gp[i] + pp[i];
    }
    __syncthreads();

    if (tid < T) {
        float m = 0.f, v = 0.f;
        #pragma unroll
        for (int f = 0; f < FEAT; f++) { float val = s[tid * FEAT + f]; m += val; v += val * val; }
        m *= (1.f / FEAT);
        v = v * (1.f / FEAT) - m * m;
        mu[tid] = m;
        rs[tid] = rsqrtf(v + LN_EPS);
    }
    __syncthreads();
    #pragma unroll
    for (int i = tid; i < T * FEAT; i += 256) {
        const int t = i >> 6, f = i & 63;
        s[i] = (s[i] - mu[t]) * rs[t] * gamma[f] + beta[f];
    }
    __syncthreads();

    #pragma unroll
    for (int i = tid; i < T * 2 * DH; i += 256) {
        const int t = i >> 7;
        const int o = i & 127;
        float acc = 0.f;
        #pragma unroll
        for (int f = 0; f < FEAT; f++) acc += s[t * FEAT + f] * __ldg(&Wqk[f * (2 * DH) + o]);
        qk[t * (2 * DH) + o] = acc;
    }
    __syncthreads();

    {
        const int i = tid >> 4;
        const int j = tid & 15;
        float d = 0.f;
        #pragma unroll
        for (int k = 0; k < DH; k++) d += qk[i * (2 * DH) + k] * qk[j * (2 * DH) + DH + k];
        d *= 0.125f;

        float mx = d;
        #pragma unroll
        for (int m = 8; m; m >>= 1) mx = fmaxf(mx, __shfl_xor_sync(0xffffffffu, mx, m, 16));
        float e = __expf(d - mx);
        float ss = e;
        #pragma unroll
        for (int m = 8; m; m >>= 1) ss += __shfl_xor_sync(0xffffffffu, ss, m, 16);

        const float w = e / ss;
        ull wp;
        asm("mov.b64 %0, {%1, %1};" : "=l"(wp) : "f"(w));
        g_attn2[bc * (T * T) + i * T + j] = wp;
    }
}

// ---------------------------------------------------------------------------
// Role: output for 224 float2 positions of one (b,c). 256 threads (224 act).
// xv[16] packed float2 (32 regs), weights via broadcast LDS.128, x L2-hot.
// ---------------------------------------------------------------------------
__device__ __forceinline__ void out_role(ull* a2,
                                         const float* __restrict__ x,
                                         float* __restrict__ out,
                                         int oid)
{
    const int bc   = oid / 7;        // caller adds bc0
    const int pblk = oid % 7;
    const int tid  = threadIdx.x;

    a2[tid] = g_attn2[bc * (T * T) + tid];   // 256 entries, 256 threads
    __syncthreads();

    if (tid >= 224) return;
    const int p2 = pblk * 224 + tid;         // [0, 1568)

    const int b = bc >> 6;
    const int c = bc & 63;

    const ull* xb2 = reinterpret_cast<const ull*>(x);
    ull*       ob2 = reinterpret_cast<ull*>(out);
    const int base2 = (b * T * C + c) * HW2 + p2;
    const int tstr2 = C * HW2;               // compile-time

    ull xv[T];
    #pragma unroll
    for (int j = 0; j < T; j++)
        xv[j] = __ldg(&xb2[base2 + j * tstr2]);

    #pragma unroll
    for (int t = 0; t < T; t++) {
        ull acc = xv[t];                     // residual
        #pragma unroll
        for (int jc = 0; jc < T; jc += 2) {
            const ulonglong2 w =
                *reinterpret_cast<const ulonglong2*>(&a2[t * T + jc]);
            acc = ffma2(w.x, xv[jc    ], acc);
            acc = ffma2(w.y, xv[jc + 1], acc);
        }
        ob2[base2 + t * tstr2] = acc;
    }
}

// ---------------------------------------------------------------------------
// Pipelined mega-kernel: block role by index. pool & out interleaved 16:7
// (mod-23 exact mapping) so reads and writes overlap at DRAM; attn at tail.
// ---------------------------------------------------------------------------
__global__ __launch_bounds__(256, 4)
void pipe_kernel(const float* __restrict__ x,
                 const float* __restrict__ pos,
                 const float* __restrict__ Wqk,
                 const float* __restrict__ gamma,
                 const float* __restrict__ beta,
                 float* __restrict__ out,
                 int pool_b0, int attn_b0, int out_b0)
{
    __shared__ __align__(16) float smf[3200];   // 12.8 KB union buffer

    const int n_pool = (pool_b0 >= 0) ? NB_POOL : 0;
    const int n_out  = (out_b0  >= 0) ? NB_OUT  : 0;
    const int n_il   = n_pool + n_out;
    const int idx    = blockIdx.x;

    if (idx >= n_il) {
        // attn role
        attn_role(smf, pos, Wqk, gamma, beta, attn_b0 * C + (idx - n_il));
        return;
    }

    int pool_id = -1, out_id = -1;
    if (n_pool && n_out) {
        const int q = idx / 23, r = idx % 23;    // 23*128 = 2944 = n_il
        if (r < 7) out_id = q * 7 + r;           // [0, 896)
        else       pool_id = q * 16 + (r - 7);   // [0, 2048)
    } else if (n_pool) {
        pool_id = idx;
    } else {
        out_id = idx;
    }

    if (pool_id >= 0) {
        pool_role(smf, x, pool_b0 * (T * C) + pool_id);
    } else {
        out_role(reinterpret_cast<ull*>(smf), x, out,
                 out_b0 * C * 7 + out_id);       // oid/7 yields bc directly
    }
}

// ---------------------------------------------------------------------------
extern "C" void kernel_launch(void* const* d_in, const int* in_sizes, int n_in,
                              void* d_out, int out_size)
{
    const float* x     = (const float*)d_in[0];   // (8,16,64,56,56)
    const float* pos   = (const float*)d_in[1];   // (512,16,64)
    const float* Wqk   = (const float*)d_in[2];   // (64,128)
    const float* gamma = (const float*)d_in[3];   // (64,)
    const float* beta  = (const float*)d_in[4];   // (64,)
    float*       out   = (float*)d_out;

    // Software pipeline over 4 chunks (b = 0,2,4,6):
    //   L: pool(i) | attn(i-1) | out(i-2)  — deps honored by launch order.
    const int sched[6][3] = {
        { 0, -1, -1},
        { 2,  0, -1},
        { 4,  2,  0},
        { 6,  4,  2},
        {-1,  6,  4},
        {-1, -1,  6},
    };
    for (int l = 0; l < 6; l++) {
        const int pb = sched[l][0], ab = sched[l][1], ob = sched[l][2];
        const int nb = (pb >= 0 ? NB_POOL : 0) + (ob >= 0 ? NB_OUT : 0)
                     + (ab >= 0 ? NB_ATTN : 0);
        pipe_kernel<<<nb, 256>>>(x, pos, Wqk, gamma, beta, out, pb, ab, ob);
    }
}

// round 16
// speedup vs baseline: 1.8588x; 1.8588x over previous
#include <cuda_runtime.h>
#include <cuda_bf16.h>

// Fixed problem shapes
#define B    8
#define T    16
#define C    64
#define H    56
#define W_   56
#define HW   (H * W_)          // 3136
#define HW4  (HW / 4)          // 784 (float4)
#define DIM  8
#define POOL 7
#define FEAT (DIM * DIM)       // 64
#define DH   64
#define BC   (B * C)           // 512
#define BTC  (B * T * C)       // 8192
#define LN_EPS 1e-5f

typedef unsigned long long ull;

// Static device scratch (no allocations allowed)
__device__ float g_pool[BC * T * FEAT];   // 2 MB
__device__ ull   g_attn2[BC * T * T];     // packed {w,w}, 1 MB

__device__ __forceinline__ ull ffma2(ull a, ull b, ull c)
{
    ull d;
    asm("fma.rn.f32x2 %0, %1, %2, %3;" : "=l"(d) : "l"(a), "l"(b), "l"(c));
    return d;
}

union F4U { float4 f; ull u[2]; };

// ---------------------------------------------------------------------------
// K1: FULL grid (8192 blocks) — measured 20 us @ 5.15 TB/s. One CTA per
// (b,t,c) slice; 12.5 KB smem stage; compile-time 7x7 reduce offsets.
// Leaves the last ~100 MB of x (chunks 1-3) resident in L2.
// ---------------------------------------------------------------------------
__global__ __launch_bounds__(256, 8)
void pool_kernel(const float* __restrict__ x)
{
    const int slice = blockIdx.x;            // ((b*T + t)*C + c)
    const int c = slice % C;
    const int t = (slice / C) % T;
    const int b = slice / (T * C);
    const int tid = threadIdx.x;

    __shared__ float stage[HW];

    const float4* xs = reinterpret_cast<const float4*>(x) + (long)slice * HW4;
    float4* st4 = reinterpret_cast<float4*>(stage);
    st4[tid]        = xs[tid];
    st4[tid + 256]  = xs[tid + 256];
    st4[tid + 512]  = xs[tid + 512];
    if (tid < 16) st4[tid + 768] = xs[tid + 768];
    __syncthreads();

    const int cell = tid >> 2;
    const int sub  = tid & 3;
    const int ci   = cell >> 3;
    const int cj   = cell & 7;

    const float* r0 = stage + (ci * POOL + sub) * W_ + cj * POOL;
    float sum = 0.f;
    #pragma unroll
    for (int jj = 0; jj < POOL; jj++) sum += r0[jj];
    if (sub < 3) {
        #pragma unroll
        for (int jj = 0; jj < POOL; jj++) sum += r0[4 * W_ + jj];
    }
    sum += __shfl_xor_sync(0xffffffffu, sum, 1);
    sum += __shfl_xor_sync(0xffffffffu, sum, 2);
    if (sub == 0)
        g_pool[((b * C + c) * T + t) * FEAT + cell] = sum * (1.f / (POOL * POOL));
}

// ---------------------------------------------------------------------------
// K2: one CTA per (b,c), full grid (512). +pos, LN, QK, dots, softmax ->
// packed {w,w} weights. ~3 us.
// ---------------------------------------------------------------------------
__global__ __launch_bounds__(256, 4)
void attn_kernel(const float* __restrict__ pos,
                 const float* __restrict__ Wqk,
                 const float* __restrict__ gamma,
                 const float* __restrict__ beta)
{
    const int bc  = blockIdx.x;
    const int tid = threadIdx.x;

    __shared__ float s[T][FEAT];
    __shared__ float qk[T][2 * DH];
    __shared__ float mu[T], rs[T];

    {
        float* sf = &s[0][0];
        const float* gp = g_pool + bc * (T * FEAT);
        const float* pp = pos    + bc * (T * FEAT);
        for (int i = tid; i < T * FEAT; i += 256) sf[i] = gp[i] + pp[i];
    }
    __syncthreads();

    if (tid < T) {
        float m = 0.f, v = 0.f;
        #pragma unroll
        for (int f = 0; f < FEAT; f++) { float val = s[tid][f]; m += val; v += val * val; }
        m *= (1.f / FEAT);
        v = v * (1.f / FEAT) - m * m;
        mu[tid] = m;
        rs[tid] = rsqrtf(v + LN_EPS);
    }
    __syncthreads();
    {
        float* sf = &s[0][0];
        for (int i = tid; i < T * FEAT; i += 256) {
            int t = i >> 6, f = i & 63;
            sf[i] = (sf[i] - mu[t]) * rs[t] * gamma[f] + beta[f];
        }
    }
    __syncthreads();

    for (int i = tid; i < T * 2 * DH; i += 256) {
        const int t = i >> 7;
        const int o = i & 127;
        float acc = 0.f;
        #pragma unroll
        for (int f = 0; f < FEAT; f++) acc += s[t][f] * __ldg(&Wqk[f * (2 * DH) + o]);
        qk[t][o] = acc;
    }
    __syncthreads();

    {
        const int i = tid >> 4;
        const int j = tid & 15;
        float d = 0.f;
        #pragma unroll
        for (int k = 0; k < DH; k++) d += qk[i][k] * qk[j][DH + k];
        d *= 0.125f;

        float mx = d;
        #pragma unroll
        for (int m = 8; m; m >>= 1) mx = fmaxf(mx, __shfl_xor_sync(0xffffffffu, mx, m, 16));
        float e = __expf(d - mx);
        float ss = e;
        #pragma unroll
        for (int m = 8; m; m >>= 1) ss += __shfl_xor_sync(0xffffffffu, ss, m, 16);

        const float w = e / ss;
        ull wp;
        asm("mov.b64 %0, {%1, %1};" : "=l"(wp) : "f"(w));
        g_attn2[bc * (T * T) + i * T + j] = wp;   // [i][j]
    }
}

// ---------------------------------------------------------------------------
// K3: full grid (7, 512) x 128 threads, REVERSED bc order: early blocks
// process bc = 511 down (the x data most recently streamed by K1 -> still
// L2-resident). One float4 position per thread, 16 independent LDG.128
// (MLP=16), packed-weight LDS.128 + FFMA2, plain float4 stores.
// ---------------------------------------------------------------------------
__global__ __launch_bounds__(128, 6)
void out_kernel(const float* __restrict__ x, float* __restrict__ out)
{
    const int bc  = (BC - 1) - blockIdx.y;    // reversed: hottest chunk first
    const int tid = threadIdx.x;

    __shared__ __align__(16) ull a2[T * T];   // 2 KB packed {w,w}
    #pragma unroll
    for (int i = tid; i < T * T; i += 128) a2[i] = g_attn2[bc * (T * T) + i];
    __syncthreads();

    const int p4 = blockIdx.x * 128 + tid;    // [0, 896), valid < 784
    if (p4 >= HW4) return;

    const int b = bc >> 6;
    const int c = bc & 63;

    const float4* xb = reinterpret_cast<const float4*>(x);
    float4*       ob = reinterpret_cast<float4*>(out);

    const int base4 = (b * T * C + c) * HW4 + p4;
    const int tstr4 = C * HW4;                // compile-time constant

    // 16 independent loads, all in flight together
    ull xv[T][2];
    #pragma unroll
    for (int j = 0; j < T; j++) {
        F4U v; v.f = __ldg(&xb[base4 + j * tstr4]);
        xv[j][0] = v.u[0];
        xv[j][1] = v.u[1];
    }

    #pragma unroll
    for (int t = 0; t < T; t++) {
        ull acc0 = xv[t][0];                  // residual
        ull acc1 = xv[t][1];
        #pragma unroll
        for (int jc = 0; jc < T; jc += 2) {
            const ulonglong2 w =
                *reinterpret_cast<const ulonglong2*>(&a2[t * T + jc]);
            acc0 = ffma2(w.x, xv[jc    ][0], acc0);
            acc1 = ffma2(w.x, xv[jc    ][1], acc1);
            acc0 = ffma2(w.y, xv[jc + 1][0], acc0);
            acc1 = ffma2(w.y, xv[jc + 1][1], acc1);
        }
        F4U r; r.u[0] = acc0; r.u[1] = acc1;
        ob[base4 + t * tstr4] = r.f;
    }
}

// ---------------------------------------------------------------------------
extern "C" void kernel_launch(void* const* d_in, const int* in_sizes, int n_in,
                              void* d_out, int out_size)
{
    const float* x     = (const float*)d_in[0];   // (8,16,64,56,56)
    const float* pos   = (const float*)d_in[1];   // (512,16,64)
    const float* Wqk   = (const float*)d_in[2];   // (64,128)
    const float* gamma = (const float*)d_in[3];   // (64,)
    const float* beta  = (const float*)d_in[4];   // (64,)
    float*       out   = (float*)d_out;

    pool_kernel<<<BTC, 256>>>(x);                       // pure read stream
    attn_kernel<<<BC, 256>>>(pos, Wqk, gamma, beta);    // tiny
    out_kernel<<<dim3(7, BC), 128>>>(x, out);           // reversed, L2-residual hits
}